// round 1
// baseline (speedup 1.0000x reference)
#include <cuda_runtime.h>
#include <cuda_bf16.h>
#include <math.h>

// Problem dims
#define BB 32
#define LL 100
#define CC 142
#define DM 512
#define DI 1024
#define NS 16
#define KC 4
#define DTR 32
#define NL 6
#define OD 128
#define MROWS (BB*LL)   // 3200
#define CPAD 144        // 142 padded to multiple of 8

// ---------------- scratch (device globals; no allocation allowed) ----------------
__device__ __align__(16) float g_h   [MROWS*DM];
__device__ __align__(16) float g_hn  [MROWS*DM];
__device__ __align__(16) float g_xz  [MROWS*2*DI];
__device__ __align__(16) float g_xc  [MROWS*DI];
__device__ __align__(16) float g_xd  [MROWS*64];
__device__ __align__(16) float g_dt  [MROWS*DI];
__device__ __align__(16) float g_yg  [MROWS*DI];
__device__ __align__(16) float g_xpad[MROWS*CPAD];
__device__ __align__(16) float g_wpad[DM*CPAD];
__device__ __align__(16) float g_last[BB*DM];
__device__ __align__(16) float g_hid [BB*DM];

// ---------------- padding for the embed GEMM (K=142 -> 144) ----------------
__global__ void pad_kernel(const float* __restrict__ x, const float* __restrict__ w)
{
    int i = blockIdx.x * 256 + threadIdx.x;
    if (i < MROWS*CPAD) {
        int m = i / CPAD, c = i % CPAD;
        g_xpad[i] = (c < CC) ? x[m*CC + c] : 0.f;
    }
    int j = i - MROWS*CPAD;
    if (j >= 0 && j < DM*CPAD) {
        int m = j / CPAD, c = j % CPAD;
        g_wpad[j] = (c < CC) ? w[m*CC + c] : 0.f;
    }
}

// ---------------- generic SGEMM: C[M,N] = A[M,K] * W[N,K]^T (+epilogue) ----------------
// EPI: 0 = store, 1 = +bias +pos(row%100), 2 = C += acc (residual), 3 = softplus(acc+bias)
template<int EPI>
__global__ void __launch_bounds__(256) sgemm_k(
    const float* __restrict__ A, int lda,
    const float* __restrict__ W, int ldw,
    float* __restrict__ C, int ldc,
    int Nn, int Kk,
    const float* __restrict__ bias,
    const float* __restrict__ pos)
{
    __shared__ float As[8][128];
    __shared__ float Bs[8][128];
    const int m0 = blockIdx.y * 128;
    const int n0 = blockIdx.x * 128;
    const int tid  = threadIdx.x;
    const int lrow = tid >> 1;
    const int lk   = (tid & 1) * 4;
    const int tx   = tid & 15;
    const int ty   = tid >> 4;

    float acc[8][8];
    #pragma unroll
    for (int i = 0; i < 8; i++)
        #pragma unroll
        for (int j = 0; j < 8; j++) acc[i][j] = 0.f;

    const bool wvalid = (n0 + lrow) < Nn;
    const float* Aptr = A + (size_t)(m0 + lrow) * lda + lk;
    const float* Wptr = W + (size_t)(wvalid ? (n0 + lrow) : 0) * ldw + lk;

    for (int k0 = 0; k0 < Kk; k0 += 8) {
        float4 av = *(const float4*)(Aptr + k0);
        float4 bv = wvalid ? *(const float4*)(Wptr + k0) : make_float4(0.f,0.f,0.f,0.f);
        __syncthreads();
        As[lk+0][lrow]=av.x; As[lk+1][lrow]=av.y; As[lk+2][lrow]=av.z; As[lk+3][lrow]=av.w;
        Bs[lk+0][lrow]=bv.x; Bs[lk+1][lrow]=bv.y; Bs[lk+2][lrow]=bv.z; Bs[lk+3][lrow]=bv.w;
        __syncthreads();
        #pragma unroll
        for (int kk = 0; kk < 8; kk++) {
            float4 a0 = *(const float4*)&As[kk][ty*8];
            float4 a1 = *(const float4*)&As[kk][ty*8+4];
            float4 b0 = *(const float4*)&Bs[kk][tx*8];
            float4 b1 = *(const float4*)&Bs[kk][tx*8+4];
            float a[8]  = {a0.x,a0.y,a0.z,a0.w,a1.x,a1.y,a1.z,a1.w};
            float bb[8] = {b0.x,b0.y,b0.z,b0.w,b1.x,b1.y,b1.z,b1.w};
            #pragma unroll
            for (int i = 0; i < 8; i++)
                #pragma unroll
                for (int j = 0; j < 8; j++)
                    acc[i][j] = fmaf(a[i], bb[j], acc[i][j]);
        }
    }

    #pragma unroll
    for (int i = 0; i < 8; i++) {
        int r = m0 + ty*8 + i;
        #pragma unroll
        for (int j = 0; j < 8; j++) {
            int c = n0 + tx*8 + j;
            if (c >= Nn) continue;
            float v = acc[i][j];
            size_t o = (size_t)r * ldc + c;
            if (EPI == 0) {
                C[o] = v;
            } else if (EPI == 1) {
                C[o] = v + bias[c] + pos[(size_t)(r % LL) * DM + c];
            } else if (EPI == 2) {
                C[o] += v;
            } else { // softplus
                float u = v + bias[c];
                C[o] = (u > 20.f) ? u : log1pf(__expf(u));
            }
        }
    }
}

// ---------------- LayerNorm over DM=512 ----------------
// row_in = blockIdx.x*rowmul + rowoff ; out row = blockIdx.x
__global__ void ln_kernel(const float* __restrict__ in, float* __restrict__ out,
                          const float* __restrict__ g, const float* __restrict__ b,
                          int rowmul, int rowoff)
{
    int row = blockIdx.x * rowmul + rowoff;
    const float* x = in + (size_t)row * DM;
    int tid = threadIdx.x; // 256
    float v0 = x[tid], v1 = x[tid + 256];
    float s  = v0 + v1;
    float sq = v0*v0 + v1*v1;
    #pragma unroll
    for (int o = 16; o; o >>= 1) {
        s  += __shfl_xor_sync(0xffffffffu, s,  o);
        sq += __shfl_xor_sync(0xffffffffu, sq, o);
    }
    __shared__ float ss[8], ssq[8];
    if ((tid & 31) == 0) { ss[tid>>5] = s; ssq[tid>>5] = sq; }
    __syncthreads();
    float ts = 0.f, tsq = 0.f;
    #pragma unroll
    for (int i = 0; i < 8; i++) { ts += ss[i]; tsq += ssq[i]; }
    float mean = ts * (1.f/DM);
    float var  = tsq * (1.f/DM) - mean*mean;
    float rs = rsqrtf(var + 1e-5f);
    size_t ob = (size_t)blockIdx.x * DM;
    out[ob + tid]       = (v0 - mean)*rs*g[tid]       + b[tid];
    out[ob + tid + 256] = (v1 - mean)*rs*g[tid + 256] + b[tid + 256];
}

// ---------------- depthwise causal conv (K=4) + bias + silu ----------------
__global__ void conv_kernel(const float* __restrict__ cw, const float* __restrict__ cb)
{
    int idx = blockIdx.x * 256 + threadIdx.x;
    if (idx >= MROWS*DI) return;
    int d = idx & (DI-1);
    int m = idx >> 10;
    int t = m % LL;
    float w0 = cw[d*4+0], w1 = cw[d*4+1], w2 = cw[d*4+2], w3 = cw[d*4+3];
    size_t rb = (size_t)m * (2*DI) + d;   // xp lives in cols [0,DI) of xz
    float acc = cb[d] + g_xz[rb] * w3;
    if (t >= 1) acc += g_xz[rb - 1*2*DI] * w2;
    if (t >= 2) acc += g_xz[rb - 2*2*DI] * w1;
    if (t >= 3) acc += g_xz[rb - 3*2*DI] * w0;
    float sig = 1.f / (1.f + __expf(-acc));
    g_xc[(size_t)m*DI + d] = acc * sig;
}

// ---------------- selective scan over L, fused D-skip + z-gate ----------------
// grid: (4, 32) = (d-chunk, batch); 256 threads, one (b,d) channel per thread
__global__ void __launch_bounds__(256) scan_kernel(const float* __restrict__ A_log,
                                                   const float* __restrict__ Dp)
{
    int b   = blockIdx.y;
    int tid = threadIdx.x;
    int d   = blockIdx.x * 256 + tid;
    __shared__ float sBC[2][32];   // [buf][0..15]=B, [16..31]=C

    float hs[NS], Af[NS];
    #pragma unroll
    for (int n = 0; n < NS; n++) {
        hs[n] = 0.f;
        Af[n] = -__expf(A_log[(size_t)d*NS + n]);
    }
    float Dpd = Dp[d];
    size_t base = (size_t)b * LL;

    if (tid < 32) sBC[0][tid] = g_xd[base*64 + 32 + tid];
    __syncthreads();

    for (int t = 0; t < LL; t++) {
        int cur = t & 1;
        if (t < LL-1 && tid < 32)
            sBC[cur ^ 1][tid] = g_xd[(base + t + 1)*64 + 32 + tid];
        size_t m = base + t;
        float xcv = g_xc[m*DI + d];
        float dtv = g_dt[m*DI + d];
        float zv  = g_xz[m*2*DI + DI + d];
        float dtx = dtv * xcv;
        float acc = 0.f;
        #pragma unroll
        for (int n = 0; n < NS; n++) {
            float dA = __expf(dtv * Af[n]);
            hs[n] = fmaf(dA, hs[n], dtx * sBC[cur][n]);
            acc = fmaf(hs[n], sBC[cur][16 + n], acc);
        }
        float y = acc + Dpd * xcv;
        float sig = 1.f / (1.f + __expf(-zv));
        g_yg[m*DI + d] = y * (zv * sig);
        __syncthreads();
    }
}

// ---------------- head: gelu(last @ op1^T + b1) ----------------
__global__ void head1_kernel(const float* __restrict__ w, const float* __restrict__ bias)
{
    int b = blockIdx.x;
    int j = threadIdx.x; // 512
    __shared__ float xr[DM];
    xr[j] = g_last[(size_t)b*DM + j];
    __syncthreads();
    const float4* wr = (const float4*)(w + (size_t)j*DM);
    float s = bias[j];
    #pragma unroll 4
    for (int k = 0; k < DM/4; k++) {
        float4 wv = wr[k];
        const float* xv = &xr[k*4];
        s = fmaf(wv.x, xv[0], s);
        s = fmaf(wv.y, xv[1], s);
        s = fmaf(wv.z, xv[2], s);
        s = fmaf(wv.w, xv[3], s);
    }
    // exact gelu
    g_hid[(size_t)b*DM + j] = 0.5f * s * (1.f + erff(s * 0.70710678118654752f));
}

// ---------------- head: hid @ op2^T + b2 -> output ----------------
__global__ void head2_kernel(const float* __restrict__ w, const float* __restrict__ bias,
                             float* __restrict__ out)
{
    int b = blockIdx.x;
    int o = threadIdx.x; // 128
    __shared__ float xr[DM];
    for (int k = o; k < DM; k += 128) xr[k] = g_hid[(size_t)b*DM + k];
    __syncthreads();
    const float4* wr = (const float4*)(w + (size_t)o*DM);
    float s = bias[o];
    #pragma unroll 4
    for (int k = 0; k < DM/4; k++) {
        float4 wv = wr[k];
        const float* xv = &xr[k*4];
        s = fmaf(wv.x, xv[0], s);
        s = fmaf(wv.y, xv[1], s);
        s = fmaf(wv.z, xv[2], s);
        s = fmaf(wv.w, xv[3], s);
    }
    out[(size_t)b*OD + o] = s;
}

// ---------------- launch ----------------
extern "C" void kernel_launch(void* const* d_in, const int* in_sizes, int n_in,
                              void* d_out, int out_size)
{
    const float* x      = (const float*)d_in[0];
    const float* inp_w  = (const float*)d_in[1];
    const float* inp_b  = (const float*)d_in[2];
    const float* pos    = (const float*)d_in[3];
    const float* norm_g = (const float*)d_in[4];
    const float* norm_b = (const float*)d_in[5];
    const float* in_w   = (const float*)d_in[6];
    const float* conv_w = (const float*)d_in[7];
    const float* conv_b = (const float*)d_in[8];
    const float* xproj_w= (const float*)d_in[9];
    const float* dt_w   = (const float*)d_in[10];
    const float* dt_b   = (const float*)d_in[11];
    const float* A_log  = (const float*)d_in[12];
    const float* Dp     = (const float*)d_in[13];
    const float* out_w  = (const float*)d_in[14];
    const float* lnf_g  = (const float*)d_in[15];
    const float* lnf_b  = (const float*)d_in[16];
    const float* op1_w  = (const float*)d_in[17];
    const float* op1_b  = (const float*)d_in[18];
    const float* op2_w  = (const float*)d_in[19];
    const float* op2_b  = (const float*)d_in[20];
    float* outp = (float*)d_out;

    float *p_h, *p_hn, *p_xz, *p_xc, *p_xd, *p_dt, *p_yg, *p_xpad, *p_wpad, *p_last, *p_hid;
    cudaGetSymbolAddress((void**)&p_h,    g_h);
    cudaGetSymbolAddress((void**)&p_hn,   g_hn);
    cudaGetSymbolAddress((void**)&p_xz,   g_xz);
    cudaGetSymbolAddress((void**)&p_xc,   g_xc);
    cudaGetSymbolAddress((void**)&p_xd,   g_xd);
    cudaGetSymbolAddress((void**)&p_dt,   g_dt);
    cudaGetSymbolAddress((void**)&p_yg,   g_yg);
    cudaGetSymbolAddress((void**)&p_xpad, g_xpad);
    cudaGetSymbolAddress((void**)&p_wpad, g_wpad);
    cudaGetSymbolAddress((void**)&p_last, g_last);
    cudaGetSymbolAddress((void**)&p_hid,  g_hid);

    // 1) pad x / inp_w, then embed GEMM (+bias +pos)
    {
        int total = MROWS*CPAD + DM*CPAD;
        pad_kernel<<<(total + 255)/256, 256>>>(x, inp_w);
        dim3 g(DM/128, MROWS/128);
        sgemm_k<1><<<g, 256>>>(p_xpad, CPAD, p_wpad, CPAD, p_h, DM, DM, CPAD, inp_b, pos);
    }

    // 2) layers
    for (int i = 0; i < NL; i++) {
        ln_kernel<<<MROWS, 256>>>(p_h, p_hn, norm_g + i*DM, norm_b + i*DM, 1, 0);

        dim3 g1(2*DI/128, MROWS/128);
        sgemm_k<0><<<g1, 256>>>(p_hn, DM, in_w + (size_t)i*2*DI*DM, DM,
                                p_xz, 2*DI, 2*DI, DM, nullptr, nullptr);

        conv_kernel<<<(MROWS*DI + 255)/256, 256>>>(conv_w + (size_t)i*DI*KC, conv_b + (size_t)i*DI);

        dim3 g2(1, MROWS/128);  // Nn = 64
        sgemm_k<0><<<g2, 256>>>(p_xc, DI, xproj_w + (size_t)i*64*DI, DI,
                                p_xd, 64, 64, DI, nullptr, nullptr);

        dim3 g3(DI/128, MROWS/128);
        sgemm_k<3><<<g3, 256>>>(p_xd, 64, dt_w + (size_t)i*DI*DTR, DTR,
                                p_dt, DI, DI, DTR, dt_b + (size_t)i*DI, nullptr);

        dim3 gs(DI/256, BB);
        scan_kernel<<<gs, 256>>>(A_log + (size_t)i*DI*NS, Dp + (size_t)i*DI);

        dim3 g4(DM/128, MROWS/128);
        sgemm_k<2><<<g4, 256>>>(p_yg, DI, out_w + (size_t)i*DM*DI, DI,
                                p_h, DM, DM, DI, nullptr, nullptr);
    }

    // 3) final LN on last timestep rows only, then the 2-layer head
    ln_kernel<<<BB, 256>>>(p_h, p_last, lnf_g, lnf_b, LL, LL-1);
    head1_kernel<<<BB, 512>>>(op1_w, op1_b);
    head2_kernel<<<BB, 128>>>(op2_w, op2_b, outp);
}

// round 2
// speedup vs baseline: 2.3582x; 2.3582x over previous
#include <cuda_runtime.h>
#include <cuda_bf16.h>
#include <math.h>

// Problem dims
#define BB 32
#define LL 100
#define CC 142
#define DM 512
#define DI 1024
#define NS 16
#define KC 4
#define DTR 32
#define NL 6
#define OD 128
#define MROWS (BB*LL)   // 3200
#define CPAD 144        // 142 padded to multiple of 16 (144 = 9*16)

// ---------------- scratch (device globals; no allocation allowed) ----------------
__device__ __align__(16) float g_h   [MROWS*DM];
__device__ __align__(16) float g_hn  [MROWS*DM];
__device__ __align__(16) float g_xz  [MROWS*2*DI];
__device__ __align__(16) float g_xc  [MROWS*DI];
__device__ __align__(16) float g_xd  [MROWS*64];
__device__ __align__(16) float g_xsp [4*MROWS*64];
__device__ __align__(16) float g_dt  [MROWS*DI];
__device__ __align__(16) float g_yg  [MROWS*DI];
__device__ __align__(16) float g_xpad[MROWS*CPAD];
__device__ __align__(16) float g_wpad[DM*CPAD];
__device__ __align__(16) float g_last[BB*DM];
__device__ __align__(16) float g_hid [BB*DM];

// ---------------- padding for the embed GEMM (K=142 -> 144) ----------------
__global__ void pad_kernel(const float* __restrict__ x, const float* __restrict__ w)
{
    int i = blockIdx.x * 256 + threadIdx.x;
    if (i < MROWS*CPAD) {
        int m = i / CPAD, c = i % CPAD;
        g_xpad[i] = (c < CC) ? x[m*CC + c] : 0.f;
    }
    int j = i - MROWS*CPAD;
    if (j >= 0 && j < DM*CPAD) {
        int m = j / CPAD, c = j % CPAD;
        g_wpad[j] = (c < CC) ? w[m*CC + c] : 0.f;
    }
}

// ---------------- tf32 helpers ----------------
__device__ __forceinline__ unsigned f2tf(float f) {
    unsigned u;
    asm("cvt.rna.tf32.f32 %0, %1;" : "=r"(u) : "f"(f));
    return u;
}

__device__ __forceinline__ void mma_tf32(float* c, const unsigned* a, const unsigned* b)
{
    asm volatile(
        "mma.sync.aligned.m16n8k8.row.col.f32.tf32.tf32.f32 "
        "{%0,%1,%2,%3}, {%4,%5,%6,%7}, {%8,%9}, {%0,%1,%2,%3};"
        : "+f"(c[0]), "+f"(c[1]), "+f"(c[2]), "+f"(c[3])
        : "r"(a[0]), "r"(a[1]), "r"(a[2]), "r"(a[3]),
          "r"(b[0]), "r"(b[1]));
}

// ---------------- TF32 tensor-core GEMM ----------------
// C[M,N] = A[M,K] * W[N,K]^T (+epilogue). 128x128 block tile, BK=16,
// 256 threads = 8 warps in 2x4, warp tile 64x32 (4x4 m16n8k8 tiles).
// Smem holds operands pre-permuted into mma fragment order:
//   As[2][kstep(2)][mtile(8)][lane(32)][reg(4)]  (float/tf32 bits)
//   Bs[2][kstep(2)][ntile(16)][lane(32)][reg(2)]
// blockIdx.z = split-K slice: A/W column offset z*Kk, C offset z*cOff.
// EPI: 0 = store, 1 = +bias +pos(row%LL), 2 = C += acc, 3 = softplus(acc+bias)
template<int EPI>
__global__ void __launch_bounds__(256) gemm_tc(
    const float* __restrict__ A, int lda,
    const float* __restrict__ W, int ldw,
    float* __restrict__ C, int ldc,
    int Nn, int Kk, int cOff,
    const float* __restrict__ bias,
    const float* __restrict__ pos)
{
    __shared__ __align__(16) unsigned As[2][2048];
    __shared__ __align__(16) unsigned Bs[2][2048];

    const int m0  = blockIdx.y * 128;
    const int n0  = blockIdx.x * 128;
    const int z   = blockIdx.z;
    const int tid = threadIdx.x;
    const int lane = tid & 31;
    const int wid  = tid >> 5;
    const int warp_m = wid & 1;    // 0..1  -> 64 rows
    const int warp_n = wid >> 1;   // 0..3  -> 32 cols
    const int zoff = z * Kk;

    // loader mapping: two float4s per thread, ids tid and tid+256
    // id -> row = id>>2 (0..127), kb = (id&3)*4 (0,4,8,12)
    const int r0 = tid >> 2,        kb0 = (tid & 3) * 4;
    const int r1 = (tid + 256) >> 2, kb1 = ((tid + 256) & 3) * 4;

    const float* A0 = A + (size_t)(m0 + r0) * lda + zoff + kb0;
    const float* A1 = A + (size_t)(m0 + r1) * lda + zoff + kb1;
    const int w0r = (n0 + r0 < Nn) ? (n0 + r0) : 0;
    const int w1r = (n0 + r1 < Nn) ? (n0 + r1) : 0;
    const float* W0 = W + (size_t)w0r * ldw + zoff + kb0;
    const float* W1 = W + (size_t)w1r * ldw + zoff + kb1;

    // precomputed smem scatter offsets (element j adds j*? along lane dim)
    // A: base = ((kstep*8 + mtile)*32 + (row&7)*4)*4 + reg ; j stride = 4
    const int a_off0 = (((kb0 >> 3) * 8 + (r0 >> 4)) * 32 + (r0 & 7) * 4) * 4
                     + ((r0 >> 3) & 1) + ((kb0 >> 2) & 1) * 2;
    const int a_off1 = (((kb1 >> 3) * 8 + (r1 >> 4)) * 32 + (r1 & 7) * 4) * 4
                     + ((r1 >> 3) & 1) + ((kb1 >> 2) & 1) * 2;
    // B: base = ((kstep*16 + ntile)*32 + (n&7)*4)*2 + reg ; j stride = 2
    const int b_off0 = (((kb0 >> 3) * 16 + (r0 >> 3)) * 32 + (r0 & 7) * 4) * 2
                     + ((kb0 >> 2) & 1);
    const int b_off1 = (((kb1 >> 3) * 16 + (r1 >> 3)) * 32 + (r1 & 7) * 4) * 2
                     + ((kb1 >> 2) & 1);

    float acc[4][4][4];
    #pragma unroll
    for (int i = 0; i < 4; i++)
        #pragma unroll
        for (int j = 0; j < 4; j++)
            #pragma unroll
            for (int r = 0; r < 4; r++) acc[i][j][r] = 0.f;

    const int iters = Kk >> 4;

    // prologue: load k-block 0 into buffer 0
    float4 av0 = *(const float4*)A0;
    float4 av1 = *(const float4*)A1;
    float4 wv0 = *(const float4*)W0;
    float4 wv1 = *(const float4*)W1;
    {
        unsigned* as = As[0]; unsigned* bs = Bs[0];
        as[a_off0 + 0] = f2tf(av0.x); as[a_off0 + 4] = f2tf(av0.y);
        as[a_off0 + 8] = f2tf(av0.z); as[a_off0 +12] = f2tf(av0.w);
        as[a_off1 + 0] = f2tf(av1.x); as[a_off1 + 4] = f2tf(av1.y);
        as[a_off1 + 8] = f2tf(av1.z); as[a_off1 +12] = f2tf(av1.w);
        bs[b_off0 + 0] = f2tf(wv0.x); bs[b_off0 + 2] = f2tf(wv0.y);
        bs[b_off0 + 4] = f2tf(wv0.z); bs[b_off0 + 6] = f2tf(wv0.w);
        bs[b_off1 + 0] = f2tf(wv1.x); bs[b_off1 + 2] = f2tf(wv1.y);
        bs[b_off1 + 4] = f2tf(wv1.z); bs[b_off1 + 6] = f2tf(wv1.w);
    }
    __syncthreads();

    int cur = 0;
    for (int it = 0; it < iters; it++) {
        // prefetch next k-block
        if (it + 1 < iters) {
            int ko = (it + 1) << 4;
            av0 = *(const float4*)(A0 + ko);
            av1 = *(const float4*)(A1 + ko);
            wv0 = *(const float4*)(W0 + ko);
            wv1 = *(const float4*)(W1 + ko);
        }

        // compute on buffer cur
        const unsigned* as = As[cur];
        const unsigned* bs = Bs[cur];
        #pragma unroll
        for (int ks = 0; ks < 2; ks++) {
            unsigned afr[4][4], bfr[4][2];
            #pragma unroll
            for (int mt = 0; mt < 4; mt++) {
                uint4 v = *(const uint4*)&as[((ks*8 + warp_m*4 + mt)*32 + lane)*4];
                afr[mt][0]=v.x; afr[mt][1]=v.y; afr[mt][2]=v.z; afr[mt][3]=v.w;
            }
            #pragma unroll
            for (int nt = 0; nt < 4; nt++) {
                uint2 v = *(const uint2*)&bs[((ks*16 + warp_n*4 + nt)*32 + lane)*2];
                bfr[nt][0]=v.x; bfr[nt][1]=v.y;
            }
            #pragma unroll
            for (int mt = 0; mt < 4; mt++)
                #pragma unroll
                for (int nt = 0; nt < 4; nt++)
                    mma_tf32(acc[mt][nt], afr[mt], bfr[nt]);
        }

        if (it + 1 < iters) {
            unsigned* asn = As[cur ^ 1]; unsigned* bsn = Bs[cur ^ 1];
            asn[a_off0 + 0] = f2tf(av0.x); asn[a_off0 + 4] = f2tf(av0.y);
            asn[a_off0 + 8] = f2tf(av0.z); asn[a_off0 +12] = f2tf(av0.w);
            asn[a_off1 + 0] = f2tf(av1.x); asn[a_off1 + 4] = f2tf(av1.y);
            asn[a_off1 + 8] = f2tf(av1.z); asn[a_off1 +12] = f2tf(av1.w);
            bsn[b_off0 + 0] = f2tf(wv0.x); bsn[b_off0 + 2] = f2tf(wv0.y);
            bsn[b_off0 + 4] = f2tf(wv0.z); bsn[b_off0 + 6] = f2tf(wv0.w);
            bsn[b_off1 + 0] = f2tf(wv1.x); bsn[b_off1 + 2] = f2tf(wv1.y);
            bsn[b_off1 + 4] = f2tf(wv1.z); bsn[b_off1 + 6] = f2tf(wv1.w);
            __syncthreads();
            cur ^= 1;
        }
    }

    // epilogue
    float* Cz = C + (size_t)z * cOff;
    #pragma unroll
    for (int mt = 0; mt < 4; mt++) {
        #pragma unroll
        for (int rr = 0; rr < 2; rr++) {    // reg pair: rows +0 / +8
            int r = m0 + warp_m*64 + mt*16 + (lane >> 2) + rr*8;
            #pragma unroll
            for (int nt = 0; nt < 4; nt++) {
                int c = n0 + warp_n*32 + nt*8 + (lane & 3)*2;
                if (c >= Nn) continue;
                float v0 = acc[mt][nt][rr*2 + 0];
                float v1 = acc[mt][nt][rr*2 + 1];
                size_t o = (size_t)r * ldc + c;
                if (EPI == 0) {
                    Cz[o]   = v0;
                    Cz[o+1] = v1;
                } else if (EPI == 1) {
                    const float* pr = pos + (size_t)(r % LL) * DM;
                    Cz[o]   = v0 + bias[c]   + pr[c];
                    Cz[o+1] = v1 + bias[c+1] + pr[c+1];
                } else if (EPI == 2) {
                    Cz[o]   += v0;
                    Cz[o+1] += v1;
                } else {
                    float u0 = v0 + bias[c];
                    float u1 = v1 + bias[c+1];
                    Cz[o]   = (u0 > 20.f) ? u0 : log1pf(__expf(u0));
                    Cz[o+1] = (u1 > 20.f) ? u1 : log1pf(__expf(u1));
                }
            }
        }
    }
}

// ---------------- reduce 4 split-K slices of xproj into g_xd ----------------
__global__ void reduce4_kernel()
{
    int i = blockIdx.x * 256 + threadIdx.x;
    if (i < MROWS*64) {
        const int S = MROWS*64;
        g_xd[i] = (g_xsp[i] + g_xsp[i + S]) + (g_xsp[i + 2*S] + g_xsp[i + 3*S]);
    }
}

// ---------------- LayerNorm over DM=512 ----------------
__global__ void ln_kernel(const float* __restrict__ in, float* __restrict__ out,
                          const float* __restrict__ g, const float* __restrict__ b,
                          int rowmul, int rowoff)
{
    int row = blockIdx.x * rowmul + rowoff;
    const float* x = in + (size_t)row * DM;
    int tid = threadIdx.x; // 256
    float v0 = x[tid], v1 = x[tid + 256];
    float s  = v0 + v1;
    float sq = v0*v0 + v1*v1;
    #pragma unroll
    for (int o = 16; o; o >>= 1) {
        s  += __shfl_xor_sync(0xffffffffu, s,  o);
        sq += __shfl_xor_sync(0xffffffffu, sq, o);
    }
    __shared__ float ss[8], ssq[8];
    if ((tid & 31) == 0) { ss[tid>>5] = s; ssq[tid>>5] = sq; }
    __syncthreads();
    float ts = 0.f, tsq = 0.f;
    #pragma unroll
    for (int i = 0; i < 8; i++) { ts += ss[i]; tsq += ssq[i]; }
    float mean = ts * (1.f/DM);
    float var  = tsq * (1.f/DM) - mean*mean;
    float rs = rsqrtf(var + 1e-5f);
    size_t ob = (size_t)blockIdx.x * DM;
    out[ob + tid]       = (v0 - mean)*rs*g[tid]       + b[tid];
    out[ob + tid + 256] = (v1 - mean)*rs*g[tid + 256] + b[tid + 256];
}

// ---------------- depthwise causal conv (K=4) + bias + silu ----------------
__global__ void conv_kernel(const float* __restrict__ cw, const float* __restrict__ cb)
{
    int idx = blockIdx.x * 256 + threadIdx.x;
    if (idx >= MROWS*DI) return;
    int d = idx & (DI-1);
    int m = idx >> 10;
    int t = m % LL;
    float w0 = cw[d*4+0], w1 = cw[d*4+1], w2 = cw[d*4+2], w3 = cw[d*4+3];
    size_t rb = (size_t)m * (2*DI) + d;   // xp lives in cols [0,DI) of xz
    float acc = cb[d] + g_xz[rb] * w3;
    if (t >= 1) acc += g_xz[rb - 1*2*DI] * w2;
    if (t >= 2) acc += g_xz[rb - 2*2*DI] * w1;
    if (t >= 3) acc += g_xz[rb - 3*2*DI] * w0;
    float sig = 1.f / (1.f + __expf(-acc));
    g_xc[(size_t)m*DI + d] = acc * sig;
}

// ---------------- selective scan over L, fused D-skip + z-gate ----------------
__global__ void __launch_bounds__(256) scan_kernel(const float* __restrict__ A_log,
                                                   const float* __restrict__ Dp)
{
    int b   = blockIdx.y;
    int tid = threadIdx.x;
    int d   = blockIdx.x * 256 + tid;
    __shared__ float sBC[2][32];   // [buf][0..15]=B, [16..31]=C

    float hs[NS], Af[NS];
    #pragma unroll
    for (int n = 0; n < NS; n++) {
        hs[n] = 0.f;
        Af[n] = -__expf(A_log[(size_t)d*NS + n]);
    }
    float Dpd = Dp[d];
    size_t base = (size_t)b * LL;

    if (tid < 32) sBC[0][tid] = g_xd[base*64 + 32 + tid];
    __syncthreads();

    for (int t = 0; t < LL; t++) {
        int cur = t & 1;
        if (t < LL-1 && tid < 32)
            sBC[cur ^ 1][tid] = g_xd[(base + t + 1)*64 + 32 + tid];
        size_t m = base + t;
        float xcv = g_xc[m*DI + d];
        float dtv = g_dt[m*DI + d];
        float zv  = g_xz[m*2*DI + DI + d];
        float dtx = dtv * xcv;
        float acc = 0.f;
        #pragma unroll
        for (int n = 0; n < NS; n++) {
            float dA = __expf(dtv * Af[n]);
            hs[n] = fmaf(dA, hs[n], dtx * sBC[cur][n]);
            acc = fmaf(hs[n], sBC[cur][16 + n], acc);
        }
        float y = acc + Dpd * xcv;
        float sig = 1.f / (1.f + __expf(-zv));
        g_yg[m*DI + d] = y * (zv * sig);
        __syncthreads();
    }
}

// ---------------- head: gelu(last @ op1^T + b1) ----------------
__global__ void head1_kernel(const float* __restrict__ w, const float* __restrict__ bias)
{
    int b = blockIdx.x;
    int j = threadIdx.x; // 512
    __shared__ float xr[DM];
    xr[j] = g_last[(size_t)b*DM + j];
    __syncthreads();
    const float4* wr = (const float4*)(w + (size_t)j*DM);
    float s = bias[j];
    #pragma unroll 4
    for (int k = 0; k < DM/4; k++) {
        float4 wv = wr[k];
        const float* xv = &xr[k*4];
        s = fmaf(wv.x, xv[0], s);
        s = fmaf(wv.y, xv[1], s);
        s = fmaf(wv.z, xv[2], s);
        s = fmaf(wv.w, xv[3], s);
    }
    g_hid[(size_t)b*DM + j] = 0.5f * s * (1.f + erff(s * 0.70710678118654752f));
}

// ---------------- head: hid @ op2^T + b2 -> output ----------------
__global__ void head2_kernel(const float* __restrict__ w, const float* __restrict__ bias,
                             float* __restrict__ out)
{
    int b = blockIdx.x;
    int o = threadIdx.x; // 128
    __shared__ float xr[DM];
    for (int k = o; k < DM; k += 128) xr[k] = g_hid[(size_t)b*DM + k];
    __syncthreads();
    const float4* wr = (const float4*)(w + (size_t)o*DM);
    float s = bias[o];
    #pragma unroll 4
    for (int k = 0; k < DM/4; k++) {
        float4 wv = wr[k];
        const float* xv = &xr[k*4];
        s = fmaf(wv.x, xv[0], s);
        s = fmaf(wv.y, xv[1], s);
        s = fmaf(wv.z, xv[2], s);
        s = fmaf(wv.w, xv[3], s);
    }
    out[(size_t)b*OD + o] = s;
}

// ---------------- launch ----------------
extern "C" void kernel_launch(void* const* d_in, const int* in_sizes, int n_in,
                              void* d_out, int out_size)
{
    const float* x      = (const float*)d_in[0];
    const float* inp_w  = (const float*)d_in[1];
    const float* inp_b  = (const float*)d_in[2];
    const float* pos    = (const float*)d_in[3];
    const float* norm_g = (const float*)d_in[4];
    const float* norm_b = (const float*)d_in[5];
    const float* in_w   = (const float*)d_in[6];
    const float* conv_w = (const float*)d_in[7];
    const float* conv_b = (const float*)d_in[8];
    const float* xproj_w= (const float*)d_in[9];
    const float* dt_w   = (const float*)d_in[10];
    const float* dt_b   = (const float*)d_in[11];
    const float* A_log  = (const float*)d_in[12];
    const float* Dp     = (const float*)d_in[13];
    const float* out_w  = (const float*)d_in[14];
    const float* lnf_g  = (const float*)d_in[15];
    const float* lnf_b  = (const float*)d_in[16];
    const float* op1_w  = (const float*)d_in[17];
    const float* op1_b  = (const float*)d_in[18];
    const float* op2_w  = (const float*)d_in[19];
    const float* op2_b  = (const float*)d_in[20];
    float* outp = (float*)d_out;

    float *p_h, *p_hn, *p_xz, *p_xc, *p_xd, *p_xsp, *p_dt, *p_yg, *p_xpad, *p_wpad;
    cudaGetSymbolAddress((void**)&p_h,    g_h);
    cudaGetSymbolAddress((void**)&p_hn,   g_hn);
    cudaGetSymbolAddress((void**)&p_xz,   g_xz);
    cudaGetSymbolAddress((void**)&p_xc,   g_xc);
    cudaGetSymbolAddress((void**)&p_xd,   g_xd);
    cudaGetSymbolAddress((void**)&p_xsp,  g_xsp);
    cudaGetSymbolAddress((void**)&p_dt,   g_dt);
    cudaGetSymbolAddress((void**)&p_yg,   g_yg);
    cudaGetSymbolAddress((void**)&p_xpad, g_xpad);
    cudaGetSymbolAddress((void**)&p_wpad, g_wpad);
    float *p_last, *p_hid;
    cudaGetSymbolAddress((void**)&p_last, g_last);
    cudaGetSymbolAddress((void**)&p_hid,  g_hid);

    // 1) pad x / inp_w, then embed GEMM (+bias +pos), K=144
    {
        int total = MROWS*CPAD + DM*CPAD;
        pad_kernel<<<(total + 255)/256, 256>>>(x, inp_w);
        dim3 g(DM/128, MROWS/128);
        gemm_tc<1><<<g, 256>>>(p_xpad, CPAD, p_wpad, CPAD, p_h, DM, DM, CPAD, 0, inp_b, pos);
    }

    // 2) layers
    for (int i = 0; i < NL; i++) {
        ln_kernel<<<MROWS, 256>>>(p_h, p_hn, norm_g + i*DM, norm_b + i*DM, 1, 0);

        dim3 g1(2*DI/128, MROWS/128);
        gemm_tc<0><<<g1, 256>>>(p_hn, DM, in_w + (size_t)i*2*DI*DM, DM,
                                p_xz, 2*DI, 2*DI, DM, 0, nullptr, nullptr);

        conv_kernel<<<(MROWS*DI + 255)/256, 256>>>(conv_w + (size_t)i*DI*KC, conv_b + (size_t)i*DI);

        // xproj: split-K x4 (K=1024 -> 4 slices of 256) into g_xsp, then reduce
        dim3 g2(1, MROWS/128, 4);
        gemm_tc<0><<<g2, 256>>>(p_xc, DI, xproj_w + (size_t)i*64*DI, DI,
                                p_xsp, 64, 64, DI/4, MROWS*64, nullptr, nullptr);
        reduce4_kernel<<<(MROWS*64 + 255)/256, 256>>>();

        dim3 g3(DI/128, MROWS/128);
        gemm_tc<3><<<g3, 256>>>(p_xd, 64, dt_w + (size_t)i*DI*DTR, DTR,
                                p_dt, DI, DI, DTR, 0, dt_b + (size_t)i*DI, nullptr);

        dim3 gs(DI/256, BB);
        scan_kernel<<<gs, 256>>>(A_log + (size_t)i*DI*NS, Dp + (size_t)i*DI);

        dim3 g4(DM/128, MROWS/128);
        gemm_tc<2><<<g4, 256>>>(p_yg, DI, out_w + (size_t)i*DM*DI, DI,
                                p_h, DM, DM, DI, 0, nullptr, nullptr);
    }

    // 3) final LN on last timestep rows only, then the 2-layer head
    ln_kernel<<<BB, 256>>>(p_h, p_last, lnf_g, lnf_b, LL, LL-1);
    head1_kernel<<<BB, 512>>>(op1_w, op1_b);
    head2_kernel<<<BB, 128>>>(op2_w, op2_b, outp);
}

// round 3
// speedup vs baseline: 2.6791x; 1.1361x over previous
#include <cuda_runtime.h>
#include <cuda_bf16.h>
#include <math.h>

// Problem dims
#define BB 32
#define LL 100
#define CC 142
#define DM 512
#define DI 1024
#define NS 16
#define KC 4
#define DTR 32
#define NL 6
#define OD 128
#define MROWS (BB*LL)   // 3200
#define CPAD 144        // 142 padded to multiple of 16

#define STAGES 3
#define SROW 20                      // padded row stride (floats) -> conflict-free
#define TILE_F (128*SROW)            // floats per tile per stage
#define SMEM_BYTES (STAGES*2*TILE_F*4)

// ---------------- scratch (device globals; no allocation allowed) ----------------
__device__ __align__(16) float g_h   [MROWS*DM];
__device__ __align__(16) float g_hn  [MROWS*DM];
__device__ __align__(16) float g_xz  [MROWS*2*DI];
__device__ __align__(16) float g_xc  [MROWS*DI];
__device__ __align__(16) float g_xd  [MROWS*64];
__device__ __align__(16) float g_xsp [4*MROWS*64];
__device__ __align__(16) float g_dt  [MROWS*DI];
__device__ __align__(16) float g_yg  [MROWS*DI];
__device__ __align__(16) float g_xpad[MROWS*CPAD];
__device__ __align__(16) float g_wpad[DM*CPAD];
__device__ __align__(16) float g_last[BB*DM];
__device__ __align__(16) float g_hid [BB*DM];

// ---------------- padding for the embed GEMM (K=142 -> 144) ----------------
__global__ void pad_kernel(const float* __restrict__ x, const float* __restrict__ w)
{
    int i = blockIdx.x * 256 + threadIdx.x;
    if (i < MROWS*CPAD) {
        int m = i / CPAD, c = i % CPAD;
        g_xpad[i] = (c < CC) ? x[m*CC + c] : 0.f;
    }
    int j = i - MROWS*CPAD;
    if (j >= 0 && j < DM*CPAD) {
        int m = j / CPAD, c = j % CPAD;
        g_wpad[j] = (c < CC) ? w[m*CC + c] : 0.f;
    }
}

// ---------------- mma + cp.async helpers ----------------
__device__ __forceinline__ void mma_tf32(float* c, const unsigned* a, const unsigned* b)
{
    asm volatile(
        "mma.sync.aligned.m16n8k8.row.col.f32.tf32.tf32.f32 "
        "{%0,%1,%2,%3}, {%4,%5,%6,%7}, {%8,%9}, {%0,%1,%2,%3};"
        : "+f"(c[0]), "+f"(c[1]), "+f"(c[2]), "+f"(c[3])
        : "r"(a[0]), "r"(a[1]), "r"(a[2]), "r"(a[3]),
          "r"(b[0]), "r"(b[1]));
}

__device__ __forceinline__ void cp16(unsigned dst, const float* src)
{
    asm volatile("cp.async.cg.shared.global [%0], [%1], 16;\n" :: "r"(dst), "l"(src));
}
__device__ __forceinline__ void cp_commit() { asm volatile("cp.async.commit_group;\n"); }
template<int N>
__device__ __forceinline__ void cp_wait() { asm volatile("cp.async.wait_group %0;\n" :: "n"(N)); }

// ---------------- TF32 tensor-core GEMM, cp.async 3-stage pipeline ----------------
// C[M,N] = A[M,K] * W[N,K]^T (+epilogue). 128x128 tile, BK=16, 256 thr = 8 warps (2x4),
// warp tile 64x32. Smem tiles row-major [128][20] (pad->conflict-free scalar LDS).
// fp32 bits fed to tf32 mma directly (HW truncates mantissa).
// blockIdx.z = split-K slice: A/W column offset z*Kk, C offset z*cOff.
// EPI: 0 = store, 1 = +bias +pos(row%LL), 2 = C += acc, 3 = softplus(acc+bias)
template<int EPI>
__global__ void __launch_bounds__(256) gemm_tc(
    const float* __restrict__ A, int lda,
    const float* __restrict__ W, int ldw,
    float* __restrict__ C, int ldc,
    int Nn, int Kk, int cOff,
    const float* __restrict__ bias,
    const float* __restrict__ pos)
{
    extern __shared__ __align__(16) float smem[];
    float* Asm = smem;                    // [STAGES][TILE_F]
    float* Bsm = smem + STAGES*TILE_F;

    const int m0  = blockIdx.y * 128;
    const int n0  = blockIdx.x * 128;
    const int z   = blockIdx.z;
    const int tid = threadIdx.x;
    const int lane = tid & 31;
    const int wid  = tid >> 5;
    const int warp_m = wid & 1;    // 0..1 -> 64 rows
    const int warp_n = wid >> 1;   // 0..3 -> 32 cols
    const int zoff = z * Kk;

    // loader: 16B chunks, ids tid / tid+256 ; id -> row=id>>2, kc=(id&3)*4
    const int r0 = tid >> 2,         kc0 = (tid & 3) * 4;
    const int r1 = (tid + 256) >> 2, kc1 = ((tid + 256) & 3) * 4;

    const float* A0 = A + (size_t)(m0 + r0) * lda + zoff + kc0;
    const float* A1 = A + (size_t)(m0 + r1) * lda + zoff + kc1;
    const int w0r = (n0 + r0 < Nn) ? (n0 + r0) : 0;
    const int w1r = (n0 + r1 < Nn) ? (n0 + r1) : 0;
    const float* W0 = W + (size_t)w0r * ldw + zoff + kc0;
    const float* W1 = W + (size_t)w1r * ldw + zoff + kc1;

    unsigned sA0 = (unsigned)__cvta_generic_to_shared(Asm + r0*SROW + kc0);
    unsigned sA1 = (unsigned)__cvta_generic_to_shared(Asm + r1*SROW + kc1);
    unsigned sB0 = (unsigned)__cvta_generic_to_shared(Bsm + r0*SROW + kc0);
    unsigned sB1 = (unsigned)__cvta_generic_to_shared(Bsm + r1*SROW + kc1);

    const int iters = Kk >> 4;

    // prologue: issue first STAGES-1 k-blocks
    #pragma unroll
    for (int s = 0; s < STAGES-1; s++) {
        if (s < iters) {
            int ko = s << 4;
            unsigned so = s * TILE_F * 4;
            cp16(sA0 + so, A0 + ko);
            cp16(sA1 + so, A1 + ko);
            cp16(sB0 + so, W0 + ko);
            cp16(sB1 + so, W1 + ko);
        }
        cp_commit();
    }

    float acc[4][4][4];
    #pragma unroll
    for (int i = 0; i < 4; i++)
        #pragma unroll
        for (int j = 0; j < 4; j++)
            #pragma unroll
            for (int r = 0; r < 4; r++) acc[i][j][r] = 0.f;

    const int lane_off = (lane >> 2) * SROW + (lane & 3);

    int stg = 0;
    for (int it = 0; it < iters; it++) {
        cp_wait<STAGES-2>();
        __syncthreads();

        // issue k-block it+STAGES-1 into the stage just freed
        {
            int nit = it + STAGES - 1;
            if (nit < iters) {
                int ko = nit << 4;
                int ns = stg + STAGES - 1; if (ns >= STAGES) ns -= STAGES;
                unsigned so = ns * TILE_F * 4;
                cp16(sA0 + so, A0 + ko);
                cp16(sA1 + so, A1 + ko);
                cp16(sB0 + so, W0 + ko);
                cp16(sB1 + so, W1 + ko);
            }
            cp_commit();
        }

        const unsigned* as = (const unsigned*)(Asm + stg*TILE_F) + warp_m*64*SROW + lane_off;
        const unsigned* bs = (const unsigned*)(Bsm + stg*TILE_F) + warp_n*32*SROW + lane_off;

        #pragma unroll
        for (int ks = 0; ks < 2; ks++) {
            const int k0 = ks * 8;
            unsigned afr[4][4], bfr[4][2];
            #pragma unroll
            for (int mt = 0; mt < 4; mt++) {
                const unsigned* p = as + mt*16*SROW + k0;
                afr[mt][0] = p[0];
                afr[mt][1] = p[8*SROW];
                afr[mt][2] = p[4];
                afr[mt][3] = p[8*SROW + 4];
            }
            #pragma unroll
            for (int nt = 0; nt < 4; nt++) {
                const unsigned* p = bs + nt*8*SROW + k0;
                bfr[nt][0] = p[0];
                bfr[nt][1] = p[4];
            }
            #pragma unroll
            for (int mt = 0; mt < 4; mt++)
                #pragma unroll
                for (int nt = 0; nt < 4; nt++)
                    mma_tf32(acc[mt][nt], afr[mt], bfr[nt]);
        }

        stg++; if (stg >= STAGES) stg = 0;
    }

    // epilogue
    float* Cz = C + (size_t)z * cOff;
    #pragma unroll
    for (int mt = 0; mt < 4; mt++) {
        #pragma unroll
        for (int rr = 0; rr < 2; rr++) {    // rows +0 / +8
            int r = m0 + warp_m*64 + mt*16 + (lane >> 2) + rr*8;
            #pragma unroll
            for (int nt = 0; nt < 4; nt++) {
                int c = n0 + warp_n*32 + nt*8 + (lane & 3)*2;
                if (c >= Nn) continue;
                float v0 = acc[mt][nt][rr*2 + 0];
                float v1 = acc[mt][nt][rr*2 + 1];
                size_t o = (size_t)r * ldc + c;
                if (EPI == 0) {
                    Cz[o]   = v0;
                    Cz[o+1] = v1;
                } else if (EPI == 1) {
                    const float* pr = pos + (size_t)(r % LL) * DM;
                    Cz[o]   = v0 + bias[c]   + pr[c];
                    Cz[o+1] = v1 + bias[c+1] + pr[c+1];
                } else if (EPI == 2) {
                    Cz[o]   += v0;
                    Cz[o+1] += v1;
                } else {
                    float u0 = v0 + bias[c];
                    float u1 = v1 + bias[c+1];
                    Cz[o]   = (u0 > 20.f) ? u0 : log1pf(__expf(u0));
                    Cz[o+1] = (u1 > 20.f) ? u1 : log1pf(__expf(u1));
                }
            }
        }
    }
}

// ---------------- reduce 4 split-K slices of xproj into g_xd ----------------
__global__ void reduce4_kernel()
{
    int i = blockIdx.x * 256 + threadIdx.x;
    if (i < MROWS*64) {
        const int S = MROWS*64;
        g_xd[i] = (g_xsp[i] + g_xsp[i + S]) + (g_xsp[i + 2*S] + g_xsp[i + 3*S]);
    }
}

// ---------------- LayerNorm over DM=512 ----------------
__global__ void ln_kernel(const float* __restrict__ in, float* __restrict__ out,
                          const float* __restrict__ g, const float* __restrict__ b,
                          int rowmul, int rowoff)
{
    int row = blockIdx.x * rowmul + rowoff;
    const float* x = in + (size_t)row * DM;
    int tid = threadIdx.x; // 256
    float v0 = x[tid], v1 = x[tid + 256];
    float s  = v0 + v1;
    float sq = v0*v0 + v1*v1;
    #pragma unroll
    for (int o = 16; o; o >>= 1) {
        s  += __shfl_xor_sync(0xffffffffu, s,  o);
        sq += __shfl_xor_sync(0xffffffffu, sq, o);
    }
    __shared__ float ss[8], ssq[8];
    if ((tid & 31) == 0) { ss[tid>>5] = s; ssq[tid>>5] = sq; }
    __syncthreads();
    float ts = 0.f, tsq = 0.f;
    #pragma unroll
    for (int i = 0; i < 8; i++) { ts += ss[i]; tsq += ssq[i]; }
    float mean = ts * (1.f/DM);
    float var  = tsq * (1.f/DM) - mean*mean;
    float rs = rsqrtf(var + 1e-5f);
    size_t ob = (size_t)blockIdx.x * DM;
    out[ob + tid]       = (v0 - mean)*rs*g[tid]       + b[tid];
    out[ob + tid + 256] = (v1 - mean)*rs*g[tid + 256] + b[tid + 256];
}

// ---------------- depthwise causal conv (K=4) + bias + silu ----------------
__global__ void conv_kernel(const float* __restrict__ cw, const float* __restrict__ cb)
{
    int idx = blockIdx.x * 256 + threadIdx.x;
    if (idx >= MROWS*DI) return;
    int d = idx & (DI-1);
    int m = idx >> 10;
    int t = m % LL;
    float w0 = cw[d*4+0], w1 = cw[d*4+1], w2 = cw[d*4+2], w3 = cw[d*4+3];
    size_t rb = (size_t)m * (2*DI) + d;   // xp lives in cols [0,DI) of xz
    float acc = cb[d] + g_xz[rb] * w3;
    if (t >= 1) acc += g_xz[rb - 1*2*DI] * w2;
    if (t >= 2) acc += g_xz[rb - 2*2*DI] * w1;
    if (t >= 3) acc += g_xz[rb - 3*2*DI] * w0;
    float sig = 1.f / (1.f + __expf(-acc));
    g_xc[(size_t)m*DI + d] = acc * sig;
}

// ---------------- selective scan over L, fused D-skip + z-gate ----------------
__global__ void __launch_bounds__(256) scan_kernel(const float* __restrict__ A_log,
                                                   const float* __restrict__ Dp)
{
    int b   = blockIdx.y;
    int tid = threadIdx.x;
    int d   = blockIdx.x * 256 + tid;
    __shared__ float sBC[2][32];   // [buf][0..15]=B, [16..31]=C

    float hs[NS], Af[NS];
    #pragma unroll
    for (int n = 0; n < NS; n++) {
        hs[n] = 0.f;
        Af[n] = -__expf(A_log[(size_t)d*NS + n]);
    }
    float Dpd = Dp[d];
    size_t base = (size_t)b * LL;

    if (tid < 32) sBC[0][tid] = g_xd[base*64 + 32 + tid];
    __syncthreads();

    for (int t = 0; t < LL; t++) {
        int cur = t & 1;
        if (t < LL-1 && tid < 32)
            sBC[cur ^ 1][tid] = g_xd[(base + t + 1)*64 + 32 + tid];
        size_t m = base + t;
        float xcv = g_xc[m*DI + d];
        float dtv = g_dt[m*DI + d];
        float zv  = g_xz[m*2*DI + DI + d];
        float dtx = dtv * xcv;
        float acc = 0.f;
        #pragma unroll
        for (int n = 0; n < NS; n++) {
            float dA = __expf(dtv * Af[n]);
            hs[n] = fmaf(dA, hs[n], dtx * sBC[cur][n]);
            acc = fmaf(hs[n], sBC[cur][16 + n], acc);
        }
        float y = acc + Dpd * xcv;
        float sig = 1.f / (1.f + __expf(-zv));
        g_yg[m*DI + d] = y * (zv * sig);
        __syncthreads();
    }
}

// ---------------- head: gelu(last @ op1^T + b1) ----------------
__global__ void head1_kernel(const float* __restrict__ w, const float* __restrict__ bias)
{
    int b = blockIdx.x;
    int j = threadIdx.x; // 512
    __shared__ float xr[DM];
    xr[j] = g_last[(size_t)b*DM + j];
    __syncthreads();
    const float4* wr = (const float4*)(w + (size_t)j*DM);
    float s = bias[j];
    #pragma unroll 4
    for (int k = 0; k < DM/4; k++) {
        float4 wv = wr[k];
        const float* xv = &xr[k*4];
        s = fmaf(wv.x, xv[0], s);
        s = fmaf(wv.y, xv[1], s);
        s = fmaf(wv.z, xv[2], s);
        s = fmaf(wv.w, xv[3], s);
    }
    g_hid[(size_t)b*DM + j] = 0.5f * s * (1.f + erff(s * 0.70710678118654752f));
}

// ---------------- head: hid @ op2^T + b2 -> output ----------------
__global__ void head2_kernel(const float* __restrict__ w, const float* __restrict__ bias,
                             float* __restrict__ out)
{
    int b = blockIdx.x;
    int o = threadIdx.x; // 128
    __shared__ float xr[DM];
    for (int k = o; k < DM; k += 128) xr[k] = g_hid[(size_t)b*DM + k];
    __syncthreads();
    const float4* wr = (const float4*)(w + (size_t)o*DM);
    float s = bias[o];
    #pragma unroll 4
    for (int k = 0; k < DM/4; k++) {
        float4 wv = wr[k];
        const float* xv = &xr[k*4];
        s = fmaf(wv.x, xv[0], s);
        s = fmaf(wv.y, xv[1], s);
        s = fmaf(wv.z, xv[2], s);
        s = fmaf(wv.w, xv[3], s);
    }
    out[(size_t)b*OD + o] = s;
}

// ---------------- launch ----------------
extern "C" void kernel_launch(void* const* d_in, const int* in_sizes, int n_in,
                              void* d_out, int out_size)
{
    const float* x      = (const float*)d_in[0];
    const float* inp_w  = (const float*)d_in[1];
    const float* inp_b  = (const float*)d_in[2];
    const float* pos    = (const float*)d_in[3];
    const float* norm_g = (const float*)d_in[4];
    const float* norm_b = (const float*)d_in[5];
    const float* in_w   = (const float*)d_in[6];
    const float* conv_w = (const float*)d_in[7];
    const float* conv_b = (const float*)d_in[8];
    const float* xproj_w= (const float*)d_in[9];
    const float* dt_w   = (const float*)d_in[10];
    const float* dt_b   = (const float*)d_in[11];
    const float* A_log  = (const float*)d_in[12];
    const float* Dp     = (const float*)d_in[13];
    const float* out_w  = (const float*)d_in[14];
    const float* lnf_g  = (const float*)d_in[15];
    const float* lnf_b  = (const float*)d_in[16];
    const float* op1_w  = (const float*)d_in[17];
    const float* op1_b  = (const float*)d_in[18];
    const float* op2_w  = (const float*)d_in[19];
    const float* op2_b  = (const float*)d_in[20];
    float* outp = (float*)d_out;

    float *p_h, *p_hn, *p_xz, *p_xc, *p_xd, *p_xsp, *p_dt, *p_yg, *p_xpad, *p_wpad;
    cudaGetSymbolAddress((void**)&p_h,    g_h);
    cudaGetSymbolAddress((void**)&p_hn,   g_hn);
    cudaGetSymbolAddress((void**)&p_xz,   g_xz);
    cudaGetSymbolAddress((void**)&p_xc,   g_xc);
    cudaGetSymbolAddress((void**)&p_xd,   g_xd);
    cudaGetSymbolAddress((void**)&p_xsp,  g_xsp);
    cudaGetSymbolAddress((void**)&p_dt,   g_dt);
    cudaGetSymbolAddress((void**)&p_yg,   g_yg);
    cudaGetSymbolAddress((void**)&p_xpad, g_xpad);
    cudaGetSymbolAddress((void**)&p_wpad, g_wpad);
    float *p_last, *p_hid;
    cudaGetSymbolAddress((void**)&p_last, g_last);
    cudaGetSymbolAddress((void**)&p_hid,  g_hid);

    // allow >48KB dynamic smem for the pipelined GEMM
    cudaFuncSetAttribute(gemm_tc<0>, cudaFuncAttributeMaxDynamicSharedMemorySize, SMEM_BYTES);
    cudaFuncSetAttribute(gemm_tc<1>, cudaFuncAttributeMaxDynamicSharedMemorySize, SMEM_BYTES);
    cudaFuncSetAttribute(gemm_tc<2>, cudaFuncAttributeMaxDynamicSharedMemorySize, SMEM_BYTES);
    cudaFuncSetAttribute(gemm_tc<3>, cudaFuncAttributeMaxDynamicSharedMemorySize, SMEM_BYTES);

    // 1) pad x / inp_w, then embed GEMM (+bias +pos), K=144
    {
        int total = MROWS*CPAD + DM*CPAD;
        pad_kernel<<<(total + 255)/256, 256>>>(x, inp_w);
        dim3 g(DM/128, MROWS/128);
        gemm_tc<1><<<g, 256, SMEM_BYTES>>>(p_xpad, CPAD, p_wpad, CPAD, p_h, DM, DM, CPAD, 0, inp_b, pos);
    }

    // 2) layers
    for (int i = 0; i < NL; i++) {
        ln_kernel<<<MROWS, 256>>>(p_h, p_hn, norm_g + i*DM, norm_b + i*DM, 1, 0);

        dim3 g1(2*DI/128, MROWS/128);
        gemm_tc<0><<<g1, 256, SMEM_BYTES>>>(p_hn, DM, in_w + (size_t)i*2*DI*DM, DM,
                                p_xz, 2*DI, 2*DI, DM, 0, nullptr, nullptr);

        conv_kernel<<<(MROWS*DI + 255)/256, 256>>>(conv_w + (size_t)i*DI*KC, conv_b + (size_t)i*DI);

        // xproj: split-K x4 (K=1024 -> 4 slices of 256) into g_xsp, then reduce
        dim3 g2(1, MROWS/128, 4);
        gemm_tc<0><<<g2, 256, SMEM_BYTES>>>(p_xc, DI, xproj_w + (size_t)i*64*DI, DI,
                                p_xsp, 64, 64, DI/4, MROWS*64, nullptr, nullptr);
        reduce4_kernel<<<(MROWS*64 + 255)/256, 256>>>();

        dim3 g3(DI/128, MROWS/128);
        gemm_tc<3><<<g3, 256, SMEM_BYTES>>>(p_xd, 64, dt_w + (size_t)i*DI*DTR, DTR,
                                p_dt, DI, DI, DTR, 0, dt_b + (size_t)i*DI, nullptr);

        dim3 gs(DI/256, BB);
        scan_kernel<<<gs, 256>>>(A_log + (size_t)i*DI*NS, Dp + (size_t)i*DI);

        dim3 g4(DM/128, MROWS/128);
        gemm_tc<2><<<g4, 256, SMEM_BYTES>>>(p_yg, DI, out_w + (size_t)i*DM*DI, DI,
                                p_h, DM, DM, DI, 0, nullptr, nullptr);
    }

    // 3) final LN on last timestep rows only, then the 2-layer head
    ln_kernel<<<BB, 256>>>(p_h, p_last, lnf_g, lnf_b, LL, LL-1);
    head1_kernel<<<BB, 512>>>(op1_w, op1_b);
    head2_kernel<<<BB, 128>>>(op2_w, op2_b, outp);
}